// round 10
// baseline (speedup 1.0000x reference)
#include <cuda_runtime.h>

#define NCTA  296
#define BLK   256
#define BTOT  2048
#define LLEN  512
#define FDIM  64
#define GDIM  256
#define SPC   7          // sample slots per CTA (296*7 = 2072 >= 2048, rest clamped)

__device__ __forceinline__ unsigned long long ffma2(unsigned long long a,
                                                    unsigned long long b,
                                                    unsigned long long c) {
    unsigned long long d;
    asm("fma.rn.f32x2 %0, %1, %2, %3;" : "=l"(d) : "l"(a), "l"(b), "l"(c));
    return d;
}
__device__ __forceinline__ unsigned long long pack2(float lo, float hi) {
    unsigned long long r;
    asm("mov.b64 %0, {%1, %2};" : "=l"(r) : "f"(lo), "f"(hi));
    return r;
}
__device__ __forceinline__ void unpack2(unsigned long long v, float& lo, float& hi) {
    asm("mov.b64 {%0, %1}, %2;" : "=f"(lo), "=f"(hi) : "l"(v));
}
__device__ __forceinline__ float tanh_ap(float x) {
    float y;
    asm("tanh.approx.f32 %0, %1;" : "=f"(y) : "f"(x));
    return y;
}

// Quad decomposition: lanes 4q..4q+3 own hidden unit u = w*8+q.
// Lane role r = lane&3 covers k in [16r, 16r+16) for ALL 4 gate columns of u.
// acc[i] on lane r accumulates column (r^i)*64+u  (xor layout -> 3-shfl reduce).
__global__ void __launch_bounds__(BLK, 2) rnn_lstm_kernel(
    const int*   __restrict__ s,
    const float* __restrict__ W0, const float* __restrict__ b0,
    const float* __restrict__ Wi, const float* __restrict__ Wh,
    const float* __restrict__ bh, const float* __restrict__ Wa,
    const float* __restrict__ ba,
    float* __restrict__ out)
{
    __shared__ __align__(16) float hbuf[2][SPC][FDIM];
    __shared__ __align__(16) float parts[2][SPC][16];
    __shared__ int toks[SPC][LLEN];

    const int tid  = threadIdx.x;
    const int w    = tid >> 5;
    const int lane = tid & 31;
    const int r    = lane & 3;       // k-quarter AND xor-col base
    const int un   = lane >> 2;      // unit within warp (0..7)
    const int u    = w * 8 + un;     // hidden unit 0..63
    const int cta  = blockIdx.x;

    // ---- weights: w2[i][j] = Wh[k..k+1][col(r^i)] for k = 16r+2j ----
    unsigned long long w2[4][8];
    float xwp[4][2];
#pragma unroll
    for (int i = 0; i < 4; i++) {
        const int col = ((r ^ i) << 6) + u;
#pragma unroll
        for (int j = 0; j < 8; j++) {
            int k = 16 * r + 2 * j;
            w2[i][j] = pack2(Wh[k * GDIM + col], Wh[(k + 1) * GDIM + col]);
        }
        // full-k input table for this column
        float v0 = bh[col], v1 = v0;
        for (int k = 0; k < FDIM; k++) {
            float wik = Wi[k * GDIM + col];
            float bk  = b0[k];
            v0 = fmaf(W0[k]        + bk, wik, v0);
            v1 = fmaf(W0[FDIM + k] + bk, wik, v1);
        }
        xwp[i][0] = v0; xwp[i][1] = v1;
    }
    const float wsel = (r == 3) ? Wa[2 * u + 1] : Wa[2 * u];
    const float ba0 = ba[0], ba1 = ba[1];

    // ---- stage tokens (clamped); zero h double-buffer ----
    for (int idx = tid; idx < SPC * LLEN; idx += BLK) {
        int si = idx >> 9, l = idx & (LLEN - 1);
        int b = cta * SPC + si;
        if (b >= BTOT) b = BTOT - 1;            // dummy sample, never written out
        toks[si][l] = s[b * LLEN + l];
    }
    for (int idx = tid; idx < 2 * SPC * FDIM; idx += BLK)
        (&hbuf[0][0][0])[idx] = 0.0f;

    float cst[SPC];
#pragma unroll
    for (int i = 0; i < SPC; i++) cst[i] = 0.0f;

    __syncthreads();

    float amp = 0.0f;

    for (int t = 0; t < LLEN; t++) {
        const int buf = t & 1;

#pragma unroll
        for (int si = 0; si < SPC; si++) {
            const int tok = (t == 0) ? 0 : toks[si][t - 1];
            const ulonglong2* hp =
                reinterpret_cast<const ulonglong2*>(&hbuf[buf][si][16 * r]);

            unsigned long long a0, a1, a2, a3;
            if (r == 0) {                        // one lane per quad adds input term
                a0 = pack2(tok ? xwp[0][1] : xwp[0][0], 0.0f);
                a1 = pack2(tok ? xwp[1][1] : xwp[1][0], 0.0f);
                a2 = pack2(tok ? xwp[2][1] : xwp[2][0], 0.0f);
                a3 = pack2(tok ? xwp[3][1] : xwp[3][0], 0.0f);
            } else {
                a0 = a1 = a2 = a3 = 0ull;
            }
#pragma unroll
            for (int j = 0; j < 4; j++) {        // 16 k-values, 4 cols: 32 ffma2
                ulonglong2 hv = hp[j];           // LDS.128
                a0 = ffma2(hv.x, w2[0][2 * j], a0);
                a1 = ffma2(hv.x, w2[1][2 * j], a1);
                a2 = ffma2(hv.x, w2[2][2 * j], a2);
                a3 = ffma2(hv.x, w2[3][2 * j], a3);
                a0 = ffma2(hv.y, w2[0][2 * j + 1], a0);
                a1 = ffma2(hv.y, w2[1][2 * j + 1], a1);
                a2 = ffma2(hv.y, w2[2][2 * j + 1], a2);
                a3 = ffma2(hv.y, w2[3][2 * j + 1], a3);
            }
            float p0, p1, p2, p3, lo, hi;
            unpack2(a0, lo, hi); p0 = lo + hi;
            unpack2(a1, lo, hi); p1 = lo + hi;
            unpack2(a2, lo, hi); p2 = lo + hi;
            unpack2(a3, lo, hi); p3 = lo + hi;

            // 3-shfl quad reduce: lane r ends with FULL preact of gate r
            float x  = __shfl_xor_sync(0xffffffffu, p1, 1);   // partner's col r
            float A  = p0 + x;
            float y  = __shfl_xor_sync(0xffffffffu, p3, 1);   // partner's col r^2
            float Bv = p2 + y;
            float z  = __shfl_xor_sync(0xffffffffu, Bv, 2);
            float S  = A + z;

            // gate r activation: r==2 -> tanh, else sigmoid = 0.5+0.5*tanh(x/2)
            float arg = (r == 2) ? S : 0.5f * S;
            float th  = tanh_ap(arg);
            float v   = (r == 2) ? th : fmaf(0.5f, th, 0.5f);

            float vx2  = __shfl_xor_sync(0xffffffffu, v, 2);  // i<->g, f<->o
            float prod = v * vx2;                              // r0,r2: i*g
            float igx  = __shfl_xor_sync(0xffffffffu, prod, 1);// r1,r3 get i*g
            float cn   = fmaf(v, cst[si], igx);                // valid at r==1 (f)
            if (r == 1) cst[si] = cn;
            float cnx  = __shfl_xor_sync(0xffffffffu, cn, 2);  // r==3 gets cn
            float hn   = v * tanh_ap(cnx);                     // valid at r==3 (o)
            float hnx  = __shfl_xor_sync(0xffffffffu, hn, 1);  // r==2 gets hn
            if (r == 3) hbuf[buf ^ 1][si][u] = hn;

            float hvv = (r == 2) ? hnx : hn;
            float pr  = (r >= 2) ? hvv * wsel : 0.0f;          // r2: hn*wa0, r3: hn*wa1
            pr += __shfl_xor_sync(0xffffffffu, pr, 4);
            pr += __shfl_xor_sync(0xffffffffu, pr, 8);
            pr += __shfl_xor_sync(0xffffffffu, pr, 16);
            if (lane == 2) parts[buf][si][2 * w]     = pr;
            if (lane == 3) parts[buf][si][2 * w + 1] = pr;
        }

        __syncthreads();

        // phase 3: warp w reduces sample w (lane 0), 7 warps active
        if (lane == 0 && w < SPC) {
            const float4* pp =
                reinterpret_cast<const float4*>(&parts[buf][w][0]);
            float4 qa = pp[0], qb = pp[1], qc = pp[2], qd = pp[3];
            float z0 = ba0 + qa.x + qa.z + qb.x + qb.z + qc.x + qc.z + qd.x + qd.z;
            float z1 = ba1 + qa.y + qa.w + qb.y + qb.w + qc.y + qc.w + qd.y + qd.w;
            int   tok = toks[w][t];
            float mx  = fmaxf(z0, z1);
            float lse = mx + log1pf(__expf(-fabsf(z0 - z1)));
            amp += 0.5f * ((tok ? z1 : z0) - lse);
        }
        // parts[buf] reuse at t+2 safe: all readers pass barrier(t+1) first.
    }

    if (lane == 0 && w < SPC) {
        int b = cta * SPC + w;
        if (b < BTOT) out[b] = amp;
    }
}

extern "C" void kernel_launch(void* const* d_in, const int* in_sizes, int n_in,
                              void* d_out, int out_size) {
    (void)in_sizes; (void)n_in; (void)out_size;
    rnn_lstm_kernel<<<NCTA, BLK>>>(
        (const int*)  d_in[0],            // s
        (const float*)d_in[1],            // W0
        (const float*)d_in[2],            // b0
        (const float*)d_in[3],            // Wi
        (const float*)d_in[4],            // Wh
        (const float*)d_in[5],            // bh
        (const float*)d_in[6],            // Wa
        (const float*)d_in[7],            // ba
        (float*)d_out);                   // amp (real part) float32[2048]
}

// round 11
// speedup vs baseline: 1.4396x; 1.4396x over previous
#include <cuda_runtime.h>

#define NCTA  296
#define BLK   256
#define BTOT  2048
#define LLEN  512
#define FDIM  64
#define GDIM  256
#define SPC   7
#define HPAD  72   // h row stride in floats: halves 144B apart -> disjoint banks

__device__ __forceinline__ unsigned long long ffma2(unsigned long long a,
                                                    unsigned long long b,
                                                    unsigned long long c) {
    unsigned long long d;
    asm("fma.rn.f32x2 %0, %1, %2, %3;" : "=l"(d) : "l"(a), "l"(b), "l"(c));
    return d;
}
__device__ __forceinline__ unsigned long long pack2(float lo, float hi) {
    unsigned long long r;
    asm("mov.b64 %0, {%1, %2};" : "=l"(r) : "f"(lo), "f"(hi));
    return r;
}
__device__ __forceinline__ void unpack2(unsigned long long v, float& lo, float& hi) {
    asm("mov.b64 {%0, %1}, %2;" : "=f"(lo), "=f"(hi) : "l"(v));
}
__device__ __forceinline__ float tanh_ap(float x) {
    float y;
    asm("tanh.approx.f32 %0, %1;" : "=f"(y) : "f"(x));
    return y;
}

// Lane map: q = lane>>2 -> unit u = w*8+q ; r = lane&3 -> gate.
// Lane r accumulates col (r*64+u) AND col ((r^1)*64+u) over k-half (r&1).
// One shfl_xor(1) of the second partial completes every column's 64-k dot.
__global__ void __launch_bounds__(BLK, 2) rnn_lstm_kernel(
    const int*   __restrict__ s,
    const float* __restrict__ W0, const float* __restrict__ b0,
    const float* __restrict__ Wi, const float* __restrict__ Wh,
    const float* __restrict__ bh, const float* __restrict__ Wa,
    const float* __restrict__ ba,
    float* __restrict__ out)
{
    __shared__ __align__(16) float hbuf[2][SPC][HPAD];
    __shared__ __align__(16) float parts[2][SPC][2][8];
    __shared__ int toks[SPC][LLEN];

    const int tid  = threadIdx.x;
    const int w    = tid >> 5;
    const int lane = tid & 31;
    const int r    = lane & 3;
    const int q    = lane >> 2;
    const int u    = w * 8 + q;
    const int kh   = r & 1;              // k-half this lane loads
    const int cta  = blockIdx.x;

    const int colA = (r << 6) + u;       // this lane's primary gate column
    const int colB = ((r ^ 1) << 6) + u; // partner column (same k-half)

    // ---- weights: 16 f32x2 per column over k in [32*kh, 32*kh+32) ----
    unsigned long long w2a[16], w2b[16];
#pragma unroll
    for (int j = 0; j < 16; j++) {
        int k = 32 * kh + 2 * j;
        w2a[j] = pack2(Wh[k * GDIM + colA], Wh[(k + 1) * GDIM + colA]);
        w2b[j] = pack2(Wh[k * GDIM + colB], Wh[(k + 1) * GDIM + colB]);
    }

    // ---- input table for colA (full k): xw[tok] = (W0[tok,:]+b0)@Wi[:,colA]+bh ----
    float xw0 = bh[colA], xw1 = xw0;
    for (int k = 0; k < FDIM; k++) {
        float wik = Wi[k * GDIM + colA];
        float bk  = b0[k];
        xw0 = fmaf(W0[k]        + bk, wik, xw0);
        xw1 = fmaf(W0[FDIM + k] + bk, wik, xw1);
    }

    const float wa0 = Wa[2 * u], wa1 = Wa[2 * u + 1];
    const float ba0 = ba[0],     ba1 = ba[1];

    // ---- stage tokens (clamped tail); zero h double-buffer ----
    for (int idx = tid; idx < SPC * LLEN; idx += BLK) {
        int si = idx >> 9, l = idx & (LLEN - 1);
        int b = cta * SPC + si;
        if (b >= BTOT) b = BTOT - 1;          // dummy sample, never written out
        toks[si][l] = s[b * LLEN + l];
    }
    for (int idx = tid; idx < 2 * SPC * HPAD; idx += BLK)
        (&hbuf[0][0][0])[idx] = 0.0f;

    float cst[SPC];
#pragma unroll
    for (int i = 0; i < SPC; i++) cst[i] = 0.0f;

    __syncthreads();

    float amp = 0.0f;

    for (int t = 0; t < LLEN; t++) {
        const int buf = t & 1;

#pragma unroll
        for (int si = 0; si < SPC; si++) {
            const int tok = (t == 0) ? 0 : toks[si][t - 1];

            // ---- half-k dot for two columns: 8 LDS.128, 32 FFMA2 ----
            const ulonglong2* hp = reinterpret_cast<const ulonglong2*>(
                &hbuf[buf][si][kh ? 36 : 0]);
            unsigned long long aA = 0ull, aB = 0ull;
#pragma unroll
            for (int j = 0; j < 8; j++) {
                ulonglong2 hv = hp[j];            // 2 addrs/warp, disjoint banks
                aA = ffma2(hv.x, w2a[2 * j],     aA);
                aB = ffma2(hv.x, w2b[2 * j],     aB);
                aA = ffma2(hv.y, w2a[2 * j + 1], aA);
                aB = ffma2(hv.y, w2b[2 * j + 1], aB);
            }
            float lo, hi, pA, pB;
            unpack2(aA, lo, hi); pA = lo + hi;
            unpack2(aB, lo, hi); pB = lo + hi;
            // partner's pB is colA's other half
            float S = pA + __shfl_xor_sync(0xffffffffu, pB, 1)
                         + (tok ? xw1 : xw0);

            // ---- activation: r==2 tanh, else sigmoid = 0.5+0.5*tanh(S/2) ----
            float arg = (r == 2) ? S : 0.5f * S;
            float th  = tanh_ap(arg);
            float v   = (r == 2) ? th : fmaf(0.5f, th, 0.5f);

            // ---- gate exchange: 4 broadcasts, all lanes redundant ----
            const int base = lane & ~3;
            float iv = __shfl_sync(0xffffffffu, v, base + 0);
            float fv = __shfl_sync(0xffffffffu, v, base + 1);
            float gv = __shfl_sync(0xffffffffu, v, base + 2);
            float ov = __shfl_sync(0xffffffffu, v, base + 3);

            float cn = fmaf(fv, cst[si], iv * gv);
            cst[si]  = cn;                        // identical on all 4 lanes
            float hn = ov * tanh_ap(cn);

            if (r == 0) hbuf[buf ^ 1][si][u < 32 ? u : u + 4] = hn;

            // ---- logit partials: lane r==0 carries z0, r==1 carries z1 ----
            float pr = (r == 0) ? hn * wa0 : ((r == 1) ? hn * wa1 : 0.0f);
            pr += __shfl_xor_sync(0xffffffffu, pr, 4);
            pr += __shfl_xor_sync(0xffffffffu, pr, 8);
            pr += __shfl_xor_sync(0xffffffffu, pr, 16);
            if (lane < 2) parts[buf][si][lane][w] = pr;
        }

        __syncthreads();

        // ---- phase 3: lane 0 of warp si reduces sample si ----
        if (lane == 0 && w < SPC) {
            const float4* pp =
                reinterpret_cast<const float4*>(&parts[buf][w][0][0]);
            float4 qa = pp[0], qb = pp[1], qc = pp[2], qd = pp[3];
            float z0 = ba0 + qa.x + qa.y + qa.z + qa.w + qb.x + qb.y + qb.z + qb.w;
            float z1 = ba1 + qc.x + qc.y + qc.z + qc.w + qd.x + qd.y + qd.z + qd.w;
            int   tok = toks[w][t];
            float mx  = fmaxf(z0, z1);
            float lse = mx + log1pf(__expf(-fabsf(z0 - z1)));
            amp += 0.5f * ((tok ? z1 : z0) - lse);
        }
        // parts[buf] reuse at t+2 safe: readers pass barrier(t+1) first.
    }

    if (lane == 0 && w < SPC) {
        int b = cta * SPC + w;
        if (b < BTOT) out[b] = amp;
    }
}

extern "C" void kernel_launch(void* const* d_in, const int* in_sizes, int n_in,
                              void* d_out, int out_size) {
    (void)in_sizes; (void)n_in; (void)out_size;
    rnn_lstm_kernel<<<NCTA, BLK>>>(
        (const int*)  d_in[0],            // s
        (const float*)d_in[1],            // W0
        (const float*)d_in[2],            // b0
        (const float*)d_in[3],            // Wi
        (const float*)d_in[4],            // Wh
        (const float*)d_in[5],            // bh
        (const float*)d_in[6],            // Wa
        (const float*)d_in[7],            // ba
        (float*)d_out);                   // amp (real part) float32[2048]
}